// round 1
// baseline (speedup 1.0000x reference)
#include <cuda_runtime.h>

#define B 256
#define C 50000
#define D 512
#define ALPHA 0.5f

__device__ int g_labels[B];

// Kernel 1: find the nonzero column per onehot row (exactly one == 1.0f).
// 50000 / 4 = 12500 float4 per row.
__global__ void labels_kernel(const float* __restrict__ onehot) {
    int b = blockIdx.x;
    const float4* row = reinterpret_cast<const float4*>(onehot + (size_t)b * C);
    for (int i = threadIdx.x; i < C / 4; i += blockDim.x) {
        float4 v = row[i];
        if (v.x != 0.0f) g_labels[b] = 4 * i + 0;
        if (v.y != 0.0f) g_labels[b] = 4 * i + 1;
        if (v.z != 0.0f) g_labels[b] = 4 * i + 2;
        if (v.w != 0.0f) g_labels[b] = 4 * i + 3;
    }
}

// Kernel 2: bulk copy centers -> new_centers (float4 grid-stride).
__global__ void copy_kernel(const float4* __restrict__ src,
                            float4* __restrict__ dst, int n) {
    int i = blockIdx.x * blockDim.x + threadIdx.x;
    int stride = gridDim.x * blockDim.x;
    for (; i < n; i += stride) dst[i] = src[i];
}

// Kernel 3: one block per sample. Computes result[b]; the lowest-indexed
// sample per class also rewrites that class's new_centers row.
__global__ void fixup_kernel(const float* __restrict__ x,
                             const float* __restrict__ centers,
                             float* __restrict__ result,
                             float* __restrict__ new_centers) {
    int b = blockIdx.x;
    int l = g_labels[b];

    __shared__ int s_match[B];
    __shared__ int s_cnt;
    __shared__ int s_first;
    __shared__ float s_warp[8];

    if (threadIdx.x == 0) {
        int cnt = 0, first = B;
        for (int s = 0; s < B; s++) {
            if (g_labels[s] == l) {
                s_match[cnt++] = s;
                if (s < first) first = s;
            }
        }
        s_cnt = cnt;
        s_first = first;
    }
    __syncthreads();

    const float* xb = x + (size_t)b * D;
    const float* cl = centers + (size_t)l * D;

    // result[b] = || x[b] - centers[l] ||^2
    float acc = 0.0f;
    for (int d = threadIdx.x; d < D; d += blockDim.x) {
        float df = xb[d] - cl[d];
        acc += df * df;
    }
    // warp reduce
    #pragma unroll
    for (int off = 16; off > 0; off >>= 1)
        acc += __shfl_down_sync(0xFFFFFFFFu, acc, off);
    if ((threadIdx.x & 31) == 0) s_warp[threadIdx.x >> 5] = acc;
    __syncthreads();
    if (threadIdx.x == 0) {
        float tot = 0.0f;
        int nw = blockDim.x >> 5;
        for (int w = 0; w < nw; w++) tot += s_warp[w];
        result[b] = tot;
    }

    // class-row fixup: only the first sample holding this label writes.
    if (b == s_first) {
        int n = s_cnt;
        float inv = 1.0f / ((float)n + 1.0f);
        for (int d = threadIdx.x; d < D; d += blockDim.x) {
            float sx = 0.0f;
            for (int m = 0; m < n; m++)
                sx += x[(size_t)s_match[m] * D + d];
            float c = cl[d];
            // delta = (n*c - sx) / (n+1);  new = c - ALPHA*delta
            new_centers[(size_t)l * D + d] = c - ALPHA * ((float)n * c - sx) * inv;
        }
    }
}

extern "C" void kernel_launch(void* const* d_in, const int* in_sizes, int n_in,
                              void* d_out, int out_size) {
    const float* x       = (const float*)d_in[0];
    const float* onehot  = (const float*)d_in[1];
    const float* centers = (const float*)d_in[2];

    float* result      = (float*)d_out;        // [B, 1]
    float* new_centers = (float*)d_out + B;    // [C, D]

    // 1. labels
    labels_kernel<<<B, 1024>>>(onehot);

    // 2. copy centers -> new_centers (C*D/4 = 6,400,000 float4)
    int n4 = C * D / 4;
    copy_kernel<<<1184, 256>>>(reinterpret_cast<const float4*>(centers),
                               reinterpret_cast<float4*>(new_centers), n4);

    // 3. result + per-class fixup
    fixup_kernel<<<B, 256>>>(x, centers, result, new_centers);
}

// round 2
// speedup vs baseline: 1.0800x; 1.0800x over previous
#include <cuda_runtime.h>

#define B 256
#define C 50000
#define D 512
#define ALPHA 0.5f

#define OH_SLICES 8                 // blocks per onehot row
#define NB_OH (B * OH_SLICES)       // 2048 onehot blocks
#define OH_ROW4 (C / 4)             // 12500 float4 per row
#define OH_PER_SLICE ((OH_ROW4 + OH_SLICES - 1) / OH_SLICES)  // 1563

#define COPY_PER_THREAD 8
#define NB_COPY ((C * D / 4) / (256 * COPY_PER_THREAD))  // 3125, exact
#define NB_TOTAL (NB_OH + NB_COPY)

__device__ int g_labels[B];

// Fused kernel: onehot label scan + centers->new_centers bulk copy.
__global__ void __launch_bounds__(256) fused_kernel(
    const float* __restrict__ onehot,
    const float4* __restrict__ centers4,
    float4* __restrict__ new_centers4) {
    int blk = blockIdx.x;

    if (blk < NB_OH) {
        // ---- onehot scan: find the single nonzero column of row b ----
        int b = blk >> 3;            // blk / OH_SLICES
        int slice = blk & 7;
        const float4* row = reinterpret_cast<const float4*>(onehot) +
                            (size_t)b * OH_ROW4;
        int lo = slice * OH_PER_SLICE;
        int hi = lo + OH_PER_SLICE;
        if (hi > OH_ROW4) hi = OH_ROW4;
        int found = -1;
        for (int i = lo + threadIdx.x; i < hi; i += 256) {
            float4 v = row[i];
            if (v.x != 0.0f) found = 4 * i + 0;
            if (v.y != 0.0f) found = 4 * i + 1;
            if (v.z != 0.0f) found = 4 * i + 2;
            if (v.w != 0.0f) found = 4 * i + 3;
        }
        if (found >= 0) g_labels[b] = found;
    } else {
        // ---- bulk copy: 8 float4 per thread, exact coverage ----
        int cb = blk - NB_OH;
        size_t base = (size_t)cb * (256 * COPY_PER_THREAD) + threadIdx.x;
        #pragma unroll
        for (int k = 0; k < COPY_PER_THREAD; k++) {
            size_t idx = base + (size_t)k * 256;
            new_centers4[idx] = centers4[idx];
        }
    }
}

// Fixup: result[b] = ||x[b]-centers[l]||^2; first sample per class rewrites
// that class's new_centers row (handles duplicate labels exactly).
__global__ void __launch_bounds__(256) fixup_kernel(
    const float* __restrict__ x,
    const float* __restrict__ centers,
    float* __restrict__ result,
    float* __restrict__ new_centers) {
    int b = blockIdx.x;
    int l = g_labels[b];

    __shared__ int s_match[B];
    __shared__ int s_cnt;
    __shared__ int s_first;
    __shared__ float s_warp[8];

    if (threadIdx.x == 0) {
        int cnt = 0, first = B;
        for (int s = 0; s < B; s++) {
            if (g_labels[s] == l) {
                s_match[cnt++] = s;
                if (s < first) first = s;
            }
        }
        s_cnt = cnt;
        s_first = first;
    }
    __syncthreads();

    const float* xb = x + (size_t)b * D;
    const float* cl = centers + (size_t)l * D;

    float acc = 0.0f;
    for (int d = threadIdx.x; d < D; d += 256) {
        float df = xb[d] - cl[d];
        acc += df * df;
    }
    #pragma unroll
    for (int off = 16; off > 0; off >>= 1)
        acc += __shfl_down_sync(0xFFFFFFFFu, acc, off);
    if ((threadIdx.x & 31) == 0) s_warp[threadIdx.x >> 5] = acc;
    __syncthreads();
    if (threadIdx.x == 0) {
        float tot = 0.0f;
        #pragma unroll
        for (int w = 0; w < 8; w++) tot += s_warp[w];
        result[b] = tot;
    }

    if (b == s_first) {
        int n = s_cnt;
        float inv = 1.0f / ((float)n + 1.0f);
        for (int d = threadIdx.x; d < D; d += 256) {
            float sx = 0.0f;
            for (int m = 0; m < n; m++)
                sx += x[(size_t)s_match[m] * D + d];
            float c = cl[d];
            new_centers[(size_t)l * D + d] = c - ALPHA * ((float)n * c - sx) * inv;
        }
    }
}

extern "C" void kernel_launch(void* const* d_in, const int* in_sizes, int n_in,
                              void* d_out, int out_size) {
    const float* x       = (const float*)d_in[0];
    const float* onehot  = (const float*)d_in[1];
    const float* centers = (const float*)d_in[2];

    float* result      = (float*)d_out;        // [B, 1]
    float* new_centers = (float*)d_out + B;    // [C, D]

    fused_kernel<<<NB_TOTAL, 256>>>(
        onehot,
        reinterpret_cast<const float4*>(centers),
        reinterpret_cast<float4*>(new_centers));

    fixup_kernel<<<B, 256>>>(x, centers, result, new_centers);
}

// round 3
// speedup vs baseline: 1.2082x; 1.1188x over previous
#include <cuda_runtime.h>

#define B 256
#define C 50000
#define D 512
#define ALPHA 0.5f

#define OH_SLICES 8                 // blocks per onehot row
#define NB_OH (B * OH_SLICES)       // 2048 onehot blocks
#define OH_ROW4 (C / 4)             // 12500 float4 per row
#define OH_PER_SLICE ((OH_ROW4 + OH_SLICES - 1) / OH_SLICES)  // 1563

#define COPY_PER_THREAD 8
#define NB_COPY ((C * D / 4) / (256 * COPY_PER_THREAD))  // 3125, exact
#define NB_TOTAL (NB_OH + NB_COPY)

__device__ int g_labels[B];

// Fused kernel: onehot label scan + centers->new_centers bulk copy.
// (At HBM roofline ~6.4 TB/s — do not touch.)
__global__ void __launch_bounds__(256) fused_kernel(
    const float* __restrict__ onehot,
    const float4* __restrict__ centers4,
    float4* __restrict__ new_centers4) {
    int blk = blockIdx.x;

    if (blk < NB_OH) {
        // ---- onehot scan: find the single nonzero column of row b ----
        int b = blk >> 3;            // blk / OH_SLICES
        int slice = blk & 7;
        const float4* row = reinterpret_cast<const float4*>(onehot) +
                            (size_t)b * OH_ROW4;
        int lo = slice * OH_PER_SLICE;
        int hi = lo + OH_PER_SLICE;
        if (hi > OH_ROW4) hi = OH_ROW4;
        int found = -1;
        for (int i = lo + threadIdx.x; i < hi; i += 256) {
            float4 v = row[i];
            if (v.x != 0.0f) found = 4 * i + 0;
            if (v.y != 0.0f) found = 4 * i + 1;
            if (v.z != 0.0f) found = 4 * i + 2;
            if (v.w != 0.0f) found = 4 * i + 3;
        }
        if (found >= 0) g_labels[b] = found;
    } else {
        // ---- bulk copy: 8 float4 per thread, exact coverage ----
        int cb = blk - NB_OH;
        size_t base = (size_t)cb * (256 * COPY_PER_THREAD) + threadIdx.x;
        #pragma unroll
        for (int k = 0; k < COPY_PER_THREAD; k++) {
            size_t idx = base + (size_t)k * 256;
            new_centers4[idx] = centers4[idx];
        }
    }
}

// Fixup: result[b] = ||x[b]-centers[l]||^2; first sample per class rewrites
// that class's new_centers row. Label matching is now fully parallel:
// one coalesced load of g_labels + shared-atomic match-list build.
__global__ void __launch_bounds__(256) fixup_kernel(
    const float* __restrict__ x,
    const float* __restrict__ centers,
    float* __restrict__ result,
    float* __restrict__ new_centers) {
    int b = blockIdx.x;
    int tid = threadIdx.x;

    __shared__ int s_lab[B];
    __shared__ int s_match[B];
    __shared__ int s_cnt;
    __shared__ int s_first;
    __shared__ float s_warp[8];

    // one coalesced transaction: all 256 labels
    s_lab[tid] = g_labels[tid];
    if (tid == 0) { s_cnt = 0; s_first = B; }
    __syncthreads();

    int l = s_lab[b];

    // parallel match-list build (order in s_match irrelevant for the sum)
    if (s_lab[tid] == l) {
        int pos = atomicAdd(&s_cnt, 1);
        s_match[pos] = tid;
        atomicMin(&s_first, tid);
    }
    __syncthreads();

    const float* xb = x + (size_t)b * D;
    const float* cl = centers + (size_t)l * D;

    // result[b] = || x[b] - centers[l] ||^2   (2 elements per thread)
    float acc = 0.0f;
    #pragma unroll
    for (int k = 0; k < D / 256; k++) {
        int d = tid + k * 256;
        float df = xb[d] - cl[d];
        acc += df * df;
    }
    #pragma unroll
    for (int off = 16; off > 0; off >>= 1)
        acc += __shfl_down_sync(0xFFFFFFFFu, acc, off);
    if ((tid & 31) == 0) s_warp[tid >> 5] = acc;
    __syncthreads();
    if (tid == 0) {
        float tot = 0.0f;
        #pragma unroll
        for (int w = 0; w < 8; w++) tot += s_warp[w];
        result[b] = tot;
    }

    // class-row fixup: only the lowest-indexed sample holding this label writes.
    if (b == s_first) {
        int n = s_cnt;
        float inv = 1.0f / ((float)n + 1.0f);
        #pragma unroll
        for (int k = 0; k < D / 256; k++) {
            int d = tid + k * 256;
            float sx = 0.0f;
            for (int m = 0; m < n; m++)
                sx += x[(size_t)s_match[m] * D + d];
            float c = cl[d];
            new_centers[(size_t)l * D + d] = c - ALPHA * ((float)n * c - sx) * inv;
        }
    }
}

extern "C" void kernel_launch(void* const* d_in, const int* in_sizes, int n_in,
                              void* d_out, int out_size) {
    const float* x       = (const float*)d_in[0];
    const float* onehot  = (const float*)d_in[1];
    const float* centers = (const float*)d_in[2];

    float* result      = (float*)d_out;        // [B, 1]
    float* new_centers = (float*)d_out + B;    // [C, D]

    fused_kernel<<<NB_TOTAL, 256>>>(
        onehot,
        reinterpret_cast<const float4*>(centers),
        reinterpret_cast<float4*>(new_centers));

    fixup_kernel<<<B, 256>>>(x, centers, result, new_centers);
}